// round 6
// baseline (speedup 1.0000x reference)
#include <cuda_runtime.h>
#include <cuda_bf16.h>
#include <cstdint>

// ============================================================================
// ContrastiveLoss via warp-level mma.sync bf16 m16n8k16 + ldmatrix.
// Round 6: BK=64 (16 chunks instead of 32) with 4-phase load/MMA interleave
// to halve barrier count and per-chunk serial overhead.
// scores[b,c] = sum_r max_{w<cl[c]} <A[b,r,:], S[c,w,:]> / (obj[b]+1e-6)
// ============================================================================

namespace {
constexpr int D = 1024;
constexpr int BM = 128;
constexpr int BK = 64;                    // k elems per smem chunk (4 x k16 steps)
constexpr int NCHUNK = D / BK;            // 16
constexpr int SROWB = 144;                // bytes per smem row (64 bf16 = 128B + 16B pad)
constexpr int STAGE_BYTES = BM * SROWB;   // 18432
constexpr int SMEM_TOTAL = 4 * STAGE_BYTES;   // A0 A1 B0 B1 = 73728
}

__device__ float g_scores[128 * 128];
__device__ float g_loss;

__global__ void zero_kernel(int n) {
    int i = blockIdx.x * blockDim.x + threadIdx.x;
    if (i < n) g_scores[i] = 0.0f;
    if (i == 0) g_loss = 0.0f;
}

__device__ __forceinline__ uint32_t smem_u32(const void* p) {
    uint32_t a;
    asm("{ .reg .u64 t; cvta.to.shared.u64 t, %1; cvt.u32.u64 %0, t; }" : "=r"(a) : "l"(p));
    return a;
}
__device__ __forceinline__ uint32_t pack_bf16(float lo, float hi) {
    __nv_bfloat162 h = __floats2bfloat162_rn(lo, hi);
    return *reinterpret_cast<uint32_t*>(&h);
}
__device__ __forceinline__ void ldsm_x4(uint32_t addr, uint32_t* r) {
    asm volatile("ldmatrix.sync.aligned.m8n8.x4.shared.b16 {%0,%1,%2,%3}, [%4];"
                 : "=r"(r[0]), "=r"(r[1]), "=r"(r[2]), "=r"(r[3]) : "r"(addr));
}
__device__ __forceinline__ void mma_bf16(float* c, const uint32_t* a, const uint32_t* b) {
    asm volatile(
        "mma.sync.aligned.m16n8k16.row.col.f32.bf16.bf16.f32 "
        "{%0,%1,%2,%3}, {%4,%5,%6,%7}, {%8,%9}, {%0,%1,%2,%3};"
        : "+f"(c[0]), "+f"(c[1]), "+f"(c[2]), "+f"(c[3])
        : "r"(a[0]), "r"(a[1]), "r"(a[2]), "r"(a[3]), "r"(b[0]), "r"(b[1]));
}

// A: [Bsz, R, D] -> M = Bsz*R rows (multiple of 128). Bm: [Bsz, W, D].
// CTA tile: 128 rows x 128 cols; cols = (128/WPAD) captions padded to WPAD words.
template <int WPAD>
__global__ void __launch_bounds__(256, 2)
xattn_bf16_kernel(const float* __restrict__ A, const float* __restrict__ Bm,
                  const int* __restrict__ cap_lens, const int* __restrict__ obj_nums,
                  int R, int W, int Bsz)
{
    constexpr int LOGW = (WPAD == 64) ? 6 : 5;
    constexpr int CAPS_PER_TILE = 128 / WPAD;
    constexpr int CAPS_PER_WARP = 64 / WPAD;     // 1 or 2

    extern __shared__ __align__(16) unsigned char smraw[];   // [4][STAGE_BYTES]
    const uint32_t sbase = smem_u32(smraw);

    const int tid  = threadIdx.x;
    const int wid  = tid >> 5;
    const int lane = tid & 31;
    const int g = lane >> 2;
    const int t = lane & 3;
    const int wm = wid & 3;           // warp rows wm*32..
    const int wn = wid >> 2;          // warp cols wn*64..
    const int m0 = blockIdx.x * BM;
    const int cbase = blockIdx.y * CAPS_PER_TILE;

    // ---- loader mapping: 2 threads per row; per phase each thread does 16 floats
    const int lr  = tid >> 1;                 // 0..127
    const int lkq = (tid & 1) << 4;           // 0 or 16 (within 32-col phase)
    const float* ga = A + (size_t)(m0 + lr) * D + lkq;
    const int bc = cbase + (lr >> LOGW);
    const int bw = lr & (WPAD - 1);
    const bool bvalid = bw < W;
    const float* gb = Bm + ((size_t)bc * W + bw) * D + lkq;
    const int soff_row = lr * SROWB + lkq * 2;   // + half*64 bytes

    float acc[2][8][4];
#pragma unroll
    for (int mt = 0; mt < 2; mt++)
#pragma unroll
        for (int nt = 0; nt < 8; nt++)
#pragma unroll
            for (int e = 0; e < 4; e++) acc[mt][nt][e] = 0.0f;

    // ---- ldmatrix per-lane base byte offsets (within a stage)
    uint32_t aoff[2];
#pragma unroll
    for (int mt = 0; mt < 2; mt++)
        aoff[mt] = (uint32_t)((wm * 32 + mt * 16 + (lane & 15)) * SROWB + ((lane >> 4) << 4));
    uint32_t boff[4];
#pragma unroll
    for (int nb = 0; nb < 4; nb++) {
        const int n_local = (lane & 7) + ((lane & 16) ? 8 : 0);
        const int kb = (lane & 8) ? 16 : 0;
        boff[nb] = (uint32_t)((wn * 64 + nb * 16 + n_local) * SROWB + kb);
    }

    const float4 fz = make_float4(0.f, 0.f, 0.f, 0.f);
    float4 fr[4];   // 16-float staging (A-phase and B-phase reuse it)

    auto loadA = [&](int k0, int half) {
        const float* p = ga + k0 + half * 32;
#pragma unroll
        for (int i = 0; i < 4; i++) fr[i] = *(const float4*)(p + i * 4);
    };
    auto loadB = [&](int k0, int half) {
        const float* p = gb + k0 + half * 32;
#pragma unroll
        for (int i = 0; i < 4; i++) fr[i] = bvalid ? *(const float4*)(p + i * 4) : fz;
    };
    auto storeStage = [&](int stage, int half) {
        uint32_t p[8];
#pragma unroll
        for (int i = 0; i < 4; i++) {
            p[2 * i]     = pack_bf16(fr[i].x, fr[i].y);
            p[2 * i + 1] = pack_bf16(fr[i].z, fr[i].w);
        }
        unsigned char* dst = smraw + stage * STAGE_BYTES + soff_row + half * 64;
        *(uint4*)(dst)      = make_uint4(p[0], p[1], p[2], p[3]);
        *(uint4*)(dst + 16) = make_uint4(p[4], p[5], p[6], p[7]);
    };

    auto do_ks = [&](int buf, int ks) {
        const uint32_t ko = (uint32_t)(ks * 32);      // 16 bf16 = 32 bytes
        const uint32_t abase = sbase + buf * STAGE_BYTES;
        const uint32_t bbase = sbase + (2 + buf) * STAGE_BYTES;
        uint32_t afr[2][4];
#pragma unroll
        for (int mt = 0; mt < 2; mt++) ldsm_x4(abase + aoff[mt] + ko, afr[mt]);
        uint32_t bfr[4][4];
#pragma unroll
        for (int nb = 0; nb < 4; nb++) ldsm_x4(bbase + boff[nb] + ko, bfr[nb]);
#pragma unroll
        for (int mt = 0; mt < 2; mt++)
#pragma unroll
            for (int nt = 0; nt < 8; nt++)
                mma_bf16(acc[mt][nt], afr[mt], &bfr[nt >> 1][(nt & 1) * 2]);
    };

    // prologue: fill buffer 0 (chunk 0)
    loadA(0, 0); storeStage(0, 0);
    loadA(0, 1); storeStage(0, 1);
    loadB(0, 0); storeStage(2, 0);
    loadB(0, 1); storeStage(2, 1);
    __syncthreads();

    for (int ch = 0; ch < NCHUNK; ch++) {
        const int buf = ch & 1;
        const int nxt = buf ^ 1;
        const bool more = (ch + 1 < NCHUNK);
        const int k1 = (ch + 1) * BK;

        if (more) loadA(k1, 0);
        do_ks(buf, 0);
        if (more) { storeStage(nxt, 0); loadA(k1, 1); }
        do_ks(buf, 1);
        if (more) { storeStage(nxt, 1); loadB(k1, 0); }
        do_ks(buf, 2);
        if (more) { storeStage(2 + nxt, 0); loadB(k1, 1); }
        do_ks(buf, 3);
        if (more) storeStage(2 + nxt, 1);
        __syncthreads();
    }

    // ---- epilogue: masked max over caption words, reduce over t-lanes, atomics
    int clv[2];
#pragma unroll
    for (int cap = 0; cap < CAPS_PER_WARP; cap++)
        clv[cap] = cap_lens[cbase + wn * CAPS_PER_WARP + cap];

    float mx[2][2][CAPS_PER_WARP];
#pragma unroll
    for (int mt = 0; mt < 2; mt++)
#pragma unroll
        for (int h = 0; h < 2; h++)
#pragma unroll
            for (int cap = 0; cap < CAPS_PER_WARP; cap++)
                mx[mt][h][cap] = -1e30f;

#pragma unroll
    for (int mt = 0; mt < 2; mt++)
#pragma unroll
        for (int nt = 0; nt < 8; nt++)
#pragma unroll
            for (int e = 0; e < 2; e++) {
                const int wc = nt * 8 + 2 * t + e;            // 0..63 within warp cols
                const int cap = wc >> LOGW;
                const int wpos = wc & (WPAD - 1);
                if (wpos < clv[cap]) {
                    mx[mt][0][cap] = fmaxf(mx[mt][0][cap], acc[mt][nt][e]);
                    mx[mt][1][cap] = fmaxf(mx[mt][1][cap], acc[mt][nt][2 + e]);
                }
            }

#pragma unroll
    for (int mt = 0; mt < 2; mt++)
#pragma unroll
        for (int h = 0; h < 2; h++)
#pragma unroll
            for (int cap = 0; cap < CAPS_PER_WARP; cap++) {
                float v = mx[mt][h][cap];
                v = fmaxf(v, __shfl_xor_sync(0xffffffffu, v, 1));
                v = fmaxf(v, __shfl_xor_sync(0xffffffffu, v, 2));
                if (t == 0) {
                    const int row = m0 + wm * 32 + mt * 16 + h * 8 + g;
                    const int b = row / R;
                    const float denom = (float)obj_nums[b] + 1e-6f;
                    const int c = cbase + wn * CAPS_PER_WARP + cap;
                    atomicAdd(&g_scores[b * Bsz + c], __fdividef(v, denom));
                }
            }
}

__global__ void loss_kernel(int Bsz) {
    __shared__ float red[256];
    const int tid = threadIdx.x;
    const int n = Bsz * Bsz;
    float sum = 0.0f;
    for (int idx = blockIdx.x * blockDim.x + tid; idx < n; idx += gridDim.x * blockDim.x) {
        const int i = idx / Bsz;
        const int j = idx - i * Bsz;
        if (i != j) {
            const float sc = g_scores[idx];
            const float di = g_scores[i * Bsz + i];
            const float dj = g_scores[j * Bsz + j];
            sum += fmaxf(0.0f, 0.2f + sc - di);
            sum += fmaxf(0.0f, 0.2f + sc - dj);
        }
    }
    red[tid] = sum;
    __syncthreads();
    for (int s = 128; s > 0; s >>= 1) {
        if (tid < s) red[tid] += red[tid + s];
        __syncthreads();
    }
    if (tid == 0) atomicAdd(&g_loss, red[0]);
}

__global__ void write_out_kernel(float* out, int out_size, int n) {
    const int i = blockIdx.x * blockDim.x + threadIdx.x;
    if (i >= out_size) return;
    if (out_size == n) { out[i] = g_scores[i]; return; }
    if (out_size == 1) { out[0] = g_loss; return; }
    if (i == 0) { out[0] = g_loss; return; }
    const int j = i - 1;
    out[i] = (j < n) ? g_scores[j] : 0.0f;
}

extern "C" void kernel_launch(void* const* d_in, const int* in_sizes, int n_in,
                              void* d_out, int out_size) {
    const float* im   = (const float*)d_in[0];
    const int*   im_l = (const int*)  d_in[1];
    const float* s    = (const float*)d_in[2];
    const int*   s_l  = (const int*)  d_in[3];
    const float* pred = (const float*)d_in[4];
    const int*   pr_l = (const int*)  d_in[5];
    const float* sp   = (const float*)d_in[6];
    const int*   sp_l = (const int*)  d_in[7];

    const int Bsz = in_sizes[1];                 // 128
    const int R   = in_sizes[0] / (Bsz * D);     // 36
    const int W   = in_sizes[2] / (Bsz * D);     // 50
    const int Rp  = in_sizes[4] / (Bsz * D);     // 25
    const int Wp  = in_sizes[6] / (Bsz * D);     // 30

    static bool attr_set = false;
    if (!attr_set) {
        cudaFuncSetAttribute(xattn_bf16_kernel<64>, cudaFuncAttributeMaxDynamicSharedMemorySize, SMEM_TOTAL);
        cudaFuncSetAttribute(xattn_bf16_kernel<32>, cudaFuncAttributeMaxDynamicSharedMemorySize, SMEM_TOTAL);
        attr_set = true;
    }

    zero_kernel<<<(Bsz * Bsz + 255) / 256, 256>>>(Bsz * Bsz);

    const int M1 = Bsz * R;    // 4608
    const int M2 = Bsz * Rp;   // 3200
    // part 1: W=50 -> pad 64, 2 captions per 128-col tile
    dim3 g1(M1 / BM, (Bsz * 64) / 128);
    xattn_bf16_kernel<64><<<g1, 256, SMEM_TOTAL>>>(im, s, s_l, im_l, R, W, Bsz);
    // part 2: W=30 -> pad 32, 4 captions per tile
    dim3 g2(M2 / BM, (Bsz * 32) / 128);
    xattn_bf16_kernel<32><<<g2, 256, SMEM_TOTAL>>>(pred, sp, sp_l, pr_l, Rp, Wp, Bsz);

    loss_kernel<<<32, 256>>>(Bsz);
    write_out_kernel<<<(out_size + 255) / 256, 256>>>((float*)d_out, out_size, Bsz * Bsz);
}

// round 9
// speedup vs baseline: 1.0293x; 1.0293x over previous
#include <cuda_runtime.h>
#include <cuda_bf16.h>
#include <cstdint>

// ============================================================================
// ContrastiveLoss via mma.sync bf16 m16n8k16 + ldmatrix.
// Round 9: caption-aligned minimal padding. Part 1 pads W=50 -> 56 (was 64),
// one caption per warp (7 n-tiles, ldmatrix.x2 for the odd tile). Part 2
// unchanged (32). Structure identical to the passing round-4 kernel:
// no scratch arrays, no atomicMax, launch_bounds(256,2).
// scores[b,c] = sum_r max_{w<cl[c]} <A[b,r,:], S[c,w,:]> / (obj[b]+1e-6)
// ============================================================================

namespace {
constexpr int D = 1024;
constexpr int BM = 128;
constexpr int BK = 32;                  // k elems per smem chunk (2 x k16 steps)
constexpr int NCHUNK = D / BK;          // 32
constexpr int SROW = 40;                // bf16 elems per smem row (80 B)
constexpr int STAGE_BYTES = BM * SROW * 2;   // 10240
}

__device__ float g_scores[128 * 128];
__device__ float g_loss;

__global__ void zero_kernel(int n) {
    int i = blockIdx.x * blockDim.x + threadIdx.x;
    if (i < n) g_scores[i] = 0.0f;
    if (i == 0) g_loss = 0.0f;
}

__device__ __forceinline__ uint32_t smem_u32(const void* p) {
    uint32_t a;
    asm("{ .reg .u64 t; cvta.to.shared.u64 t, %1; cvt.u32.u64 %0, t; }" : "=r"(a) : "l"(p));
    return a;
}
__device__ __forceinline__ uint32_t pack_bf16(float lo, float hi) {
    __nv_bfloat162 h = __floats2bfloat162_rn(lo, hi);
    return *reinterpret_cast<uint32_t*>(&h);
}
__device__ __forceinline__ void ldsm_x4(uint32_t addr, uint32_t* r) {
    asm volatile("ldmatrix.sync.aligned.m8n8.x4.shared.b16 {%0,%1,%2,%3}, [%4];"
                 : "=r"(r[0]), "=r"(r[1]), "=r"(r[2]), "=r"(r[3]) : "r"(addr));
}
__device__ __forceinline__ void ldsm_x2(uint32_t addr, uint32_t* r) {
    asm volatile("ldmatrix.sync.aligned.m8n8.x2.shared.b16 {%0,%1}, [%2];"
                 : "=r"(r[0]), "=r"(r[1]) : "r"(addr));
}
__device__ __forceinline__ void mma_bf16(float* c, const uint32_t* a, const uint32_t* b) {
    asm volatile(
        "mma.sync.aligned.m16n8k16.row.col.f32.bf16.bf16.f32 "
        "{%0,%1,%2,%3}, {%4,%5,%6,%7}, {%8,%9}, {%0,%1,%2,%3};"
        : "+f"(c[0]), "+f"(c[1]), "+f"(c[2]), "+f"(c[3])
        : "r"(a[0]), "r"(a[1]), "r"(a[2]), "r"(a[3]), "r"(b[0]), "r"(b[1]));
}

// A: [Bsz*R, D]; Bm: [Bsz, W, D].
// NT n-tiles (of 8 cols) per warp; WPAD words per padded caption.
// Warp cols = NT*8; captions/warp = NT*8/WPAD; CTA cols = 2*NT*8.
template <int NT, int WPAD>
__global__ void __launch_bounds__(256, 2)
xattn_bf16_kernel(const float* __restrict__ A, const float* __restrict__ Bm,
                  const int* __restrict__ cap_lens, const int* __restrict__ obj_nums,
                  int R, int W, int Bsz)
{
    constexpr int BNW = NT * 8;              // cols per warp (56 or 64)
    constexpr int BN  = 2 * BNW;             // cols per CTA (112 or 128)
    constexpr int CPW = BNW / WPAD;          // captions per warp (1 or 2)
    constexpr int CAPS_PER_TILE = 2 * CPW;
    constexpr int NB4 = NT / 2;              // full x4 B loads per ks
    constexpr bool HASX2 = (NT & 1) != 0;

    __shared__ __align__(16) unsigned char smraw[4][STAGE_BYTES]; // A0 A1 B0 B1
    const uint32_t sbase = smem_u32(smraw);

    const int tid  = threadIdx.x;
    const int wid  = tid >> 5;
    const int lane = tid & 31;
    const int g = lane >> 2;
    const int t = lane & 3;
    const int wm = wid & 3;           // warp rows wm*32..
    const int wn = wid >> 2;          // warp cols wn*BNW..
    const int m0 = blockIdx.x * BM;
    const int cbase = blockIdx.y * CAPS_PER_TILE;

    // ---- loader mapping: 2 threads per row, 16 k-floats each
    const int lr = tid >> 1;                  // 0..127
    const int lk = (tid & 1) << 4;            // 0 or 16
    const float* ga = A + (size_t)(m0 + lr) * D + lk;
    const int bcap  = lr / WPAD;              // compile-time divisor
    const int bword = lr - bcap * WPAD;
    const bool brow   = lr < BN;              // row exists in B stage
    const bool bvalid = brow && (bword < W);  // real word
    // clamp caption index so no OOB pointer is formed for lr >= BN
    const int bcap_c = (bcap < CAPS_PER_TILE) ? bcap : 0;
    const float* gb = Bm + ((size_t)(cbase + bcap_c) * W + bword) * D + lk;
    const int soff = lr * (SROW * 2) + lk * 2;

    float acc[2][NT][4];
#pragma unroll
    for (int mt = 0; mt < 2; mt++)
#pragma unroll
        for (int nt = 0; nt < NT; nt++)
#pragma unroll
            for (int e = 0; e < 4; e++) acc[mt][nt][e] = 0.0f;

    // ---- ldmatrix per-lane base byte offsets (within a stage)
    uint32_t aoff[2];
#pragma unroll
    for (int mt = 0; mt < 2; mt++)
        aoff[mt] = (uint32_t)((wm * 32 + mt * 16 + (lane & 15)) * (SROW * 2) + ((lane >> 4) << 4));
    uint32_t boff[NB4 + (HASX2 ? 1 : 0)];
#pragma unroll
    for (int nb = 0; nb < NB4; nb++) {
        const int n_local = (lane & 7) + ((lane & 16) ? 8 : 0);
        const int kb = (lane & 8) ? 16 : 0;
        boff[nb] = (uint32_t)((wn * BNW + nb * 16 + n_local) * (SROW * 2) + kb);
    }
    if (HASX2) {
        // x2: lanes 0-7 -> rows n0..n0+7 k-bytes 0; lanes 8-15 -> same rows k-bytes 16
        const int n_local = lane & 7;
        const int kb = (lane & 8) ? 16 : 0;
        boff[NB4] = (uint32_t)((wn * BNW + NB4 * 16 + n_local) * (SROW * 2) + kb);
    }

    const float4 fz = make_float4(0.f, 0.f, 0.f, 0.f);
    float4 ra[4], rb[4];
    auto load_regs = [&](int k0) {
#pragma unroll
        for (int i = 0; i < 4; i++) ra[i] = *(const float4*)(ga + k0 + i * 4);
#pragma unroll
        for (int i = 0; i < 4; i++) rb[i] = bvalid ? *(const float4*)(gb + k0 + i * 4) : fz;
    };
    auto store_smem = [&](int buf) {
        uint32_t p[8];
#pragma unroll
        for (int i = 0; i < 4; i++) {
            p[2 * i]     = pack_bf16(ra[i].x, ra[i].y);
            p[2 * i + 1] = pack_bf16(ra[i].z, ra[i].w);
        }
        *(uint4*)(&smraw[buf][soff])      = make_uint4(p[0], p[1], p[2], p[3]);
        *(uint4*)(&smraw[buf][soff + 16]) = make_uint4(p[4], p[5], p[6], p[7]);
        if (brow) {
#pragma unroll
            for (int i = 0; i < 4; i++) {
                p[2 * i]     = pack_bf16(rb[i].x, rb[i].y);
                p[2 * i + 1] = pack_bf16(rb[i].z, rb[i].w);
            }
            *(uint4*)(&smraw[2 + buf][soff])      = make_uint4(p[0], p[1], p[2], p[3]);
            *(uint4*)(&smraw[2 + buf][soff + 16]) = make_uint4(p[4], p[5], p[6], p[7]);
        }
    };

    load_regs(0);
    store_smem(0);
    __syncthreads();

    for (int ch = 0; ch < NCHUNK; ch++) {
        const int buf = ch & 1;
        if (ch + 1 < NCHUNK) load_regs((ch + 1) * BK);

        const uint32_t abase = sbase + buf * STAGE_BYTES;
        const uint32_t bbase = sbase + (2 + buf) * STAGE_BYTES;
#pragma unroll
        for (int ks = 0; ks < 2; ks++) {
            const uint32_t ko = ks * 32;
            uint32_t afr[2][4];
#pragma unroll
            for (int mt = 0; mt < 2; mt++) ldsm_x4(abase + aoff[mt] + ko, afr[mt]);
            uint32_t bfr[NB4 + (HASX2 ? 1 : 0)][4];
#pragma unroll
            for (int nb = 0; nb < NB4; nb++) ldsm_x4(bbase + boff[nb] + ko, bfr[nb]);
            if (HASX2) ldsm_x2(bbase + boff[NB4] + ko, bfr[NB4]);
#pragma unroll
            for (int mt = 0; mt < 2; mt++)
#pragma unroll
                for (int nt = 0; nt < NT; nt++)
                    mma_bf16(acc[mt][nt], afr[mt], &bfr[nt >> 1][(nt & 1) * 2]);
        }

        if (ch + 1 < NCHUNK) store_smem((ch + 1) & 1);
        __syncthreads();
    }

    // ---- epilogue: masked max over caption words, reduce over t-lanes, atomics
    int clv[CPW];
#pragma unroll
    for (int cap = 0; cap < CPW; cap++)
        clv[cap] = cap_lens[cbase + wn * CPW + cap];

    float mx[2][2][CPW];
#pragma unroll
    for (int mt = 0; mt < 2; mt++)
#pragma unroll
        for (int h = 0; h < 2; h++)
#pragma unroll
            for (int cap = 0; cap < CPW; cap++)
                mx[mt][h][cap] = -1e30f;

#pragma unroll
    for (int mt = 0; mt < 2; mt++)
#pragma unroll
        for (int nt = 0; nt < NT; nt++)
#pragma unroll
            for (int e = 0; e < 2; e++) {
                const int wc = nt * 8 + 2 * t + e;        // 0..BNW-1 within warp cols
                const int cap  = wc / WPAD;               // 0..CPW-1 (const divisor)
                const int wpos = wc - cap * WPAD;
                if (wpos < clv[cap]) {
                    mx[mt][0][cap] = fmaxf(mx[mt][0][cap], acc[mt][nt][e]);
                    mx[mt][1][cap] = fmaxf(mx[mt][1][cap], acc[mt][nt][2 + e]);
                }
            }

#pragma unroll
    for (int mt = 0; mt < 2; mt++)
#pragma unroll
        for (int h = 0; h < 2; h++)
#pragma unroll
            for (int cap = 0; cap < CPW; cap++) {
                float v = mx[mt][h][cap];
                v = fmaxf(v, __shfl_xor_sync(0xffffffffu, v, 1));
                v = fmaxf(v, __shfl_xor_sync(0xffffffffu, v, 2));
                if (t == 0) {
                    const int row = m0 + wm * 32 + mt * 16 + h * 8 + g;
                    const int b = row / R;
                    const float denom = (float)obj_nums[b] + 1e-6f;
                    const int c = cbase + wn * CPW + cap;
                    atomicAdd(&g_scores[b * Bsz + c], __fdividef(v, denom));
                }
            }
}

__global__ void loss_kernel(int Bsz) {
    __shared__ float red[256];
    const int tid = threadIdx.x;
    const int n = Bsz * Bsz;
    float sum = 0.0f;
    for (int idx = blockIdx.x * blockDim.x + tid; idx < n; idx += gridDim.x * blockDim.x) {
        const int i = idx / Bsz;
        const int j = idx - i * Bsz;
        if (i != j) {
            const float sc = g_scores[idx];
            const float di = g_scores[i * Bsz + i];
            const float dj = g_scores[j * Bsz + j];
            sum += fmaxf(0.0f, 0.2f + sc - di);
            sum += fmaxf(0.0f, 0.2f + sc - dj);
        }
    }
    red[tid] = sum;
    __syncthreads();
    for (int s = 128; s > 0; s >>= 1) {
        if (tid < s) red[tid] += red[tid + s];
        __syncthreads();
    }
    if (tid == 0) atomicAdd(&g_loss, red[0]);
}

__global__ void write_out_kernel(float* out, int out_size, int n) {
    const int i = blockIdx.x * blockDim.x + threadIdx.x;
    if (i >= out_size) return;
    if (out_size == n) { out[i] = g_scores[i]; return; }
    if (out_size == 1) { out[0] = g_loss; return; }
    if (i == 0) { out[0] = g_loss; return; }
    const int j = i - 1;
    out[i] = (j < n) ? g_scores[j] : 0.0f;
}

extern "C" void kernel_launch(void* const* d_in, const int* in_sizes, int n_in,
                              void* d_out, int out_size) {
    const float* im   = (const float*)d_in[0];
    const int*   im_l = (const int*)  d_in[1];
    const float* s    = (const float*)d_in[2];
    const int*   s_l  = (const int*)  d_in[3];
    const float* pred = (const float*)d_in[4];
    const int*   pr_l = (const int*)  d_in[5];
    const float* sp   = (const float*)d_in[6];
    const int*   sp_l = (const int*)  d_in[7];

    const int Bsz = in_sizes[1];                 // 128
    const int R   = in_sizes[0] / (Bsz * D);     // 36
    const int W   = in_sizes[2] / (Bsz * D);     // 50
    const int Rp  = in_sizes[4] / (Bsz * D);     // 25
    const int Wp  = in_sizes[6] / (Bsz * D);     // 30

    zero_kernel<<<(Bsz * Bsz + 255) / 256, 256>>>(Bsz * Bsz);

    const int M1 = Bsz * R;    // 4608
    const int M2 = Bsz * Rp;   // 3200
    // part 1: W=50 -> pad 56, one caption per warp, 2 captions per CTA tile
    dim3 g1(M1 / BM, Bsz / 2);   // (36, 64)
    xattn_bf16_kernel<7, 56><<<g1, 256>>>(im, s, s_l, im_l, R, W, Bsz);
    // part 2: W=30 -> pad 32, 2 captions per warp, 4 captions per CTA tile
    dim3 g2(M2 / BM, Bsz / 4);   // (25, 32)
    xattn_bf16_kernel<8, 32><<<g2, 256>>>(pred, sp, sp_l, pr_l, Rp, Wp, Bsz);

    loss_kernel<<<32, 256>>>(Bsz);
    write_out_kernel<<<(out_size + 255) / 256, 256>>>((float*)d_out, out_size, Bsz * Bsz);
}

// round 11
// speedup vs baseline: 1.8922x; 1.8383x over previous
#include <cuda_runtime.h>
#include <cuda_bf16.h>
#include <cstdint>

// ============================================================================
// ContrastiveLoss via mma.sync bf16 m16n8k16 + ldmatrix.
// Round 11: R10 design with DYNAMIC shared memory (3-stage cp.async ring =
// 60 KB > 48 KB static limit -> extern __shared__ + FuncSetAttribute).
// Pre-convert fp32->bf16 into __device__ scratch; cp.async feeds smem ring.
// scores[b,c] = sum_r max_{w<cl[c]} <A[b,r,:], S[c,w,:]> / (obj[b]+1e-6)
// ============================================================================

namespace {
constexpr int D = 1024;
constexpr int BM = 128;
constexpr int BK = 32;                  // k elems per chunk (2 x k16 steps)
constexpr int NCHUNK = D / BK;          // 32
constexpr int SROW = 40;                // bf16 elems per smem row (80 B)
constexpr int STAGE_BYTES = BM * SROW * 2;   // 10240
constexpr int SMEM_DYN = 6 * STAGE_BYTES;    // 61440 (A:0..2, B:3..5)
constexpr int BSZ_C = 128;
constexpr int R1 = 36, W1 = 50;
constexpr int R2 = 25, W2 = 30;
constexpr int M1 = BSZ_C * R1;          // 4608
constexpr int M2 = BSZ_C * R2;          // 3200
}

// bf16 scratch, reused between part1 and part2
__device__ __nv_bfloat16 g_Abf[M1 * D];            // 9.4 MB
__device__ __nv_bfloat16 g_Bbf[BSZ_C * W1 * D];    // 13.1 MB
__device__ float g_scores[BSZ_C * BSZ_C];
__device__ float g_loss;

__global__ void zero_kernel(int n) {
    int i = blockIdx.x * blockDim.x + threadIdx.x;
    if (i < n) g_scores[i] = 0.0f;
    if (i == 0) g_loss = 0.0f;
}

__device__ __forceinline__ uint32_t smem_u32(const void* p) {
    uint32_t a;
    asm("{ .reg .u64 t; cvta.to.shared.u64 t, %1; cvt.u32.u64 %0, t; }" : "=r"(a) : "l"(p));
    return a;
}
__device__ __forceinline__ uint32_t pack_bf16(float lo, float hi) {
    __nv_bfloat162 h = __floats2bfloat162_rn(lo, hi);
    return *reinterpret_cast<uint32_t*>(&h);
}
__device__ __forceinline__ void ldsm_x4(uint32_t addr, uint32_t* r) {
    asm volatile("ldmatrix.sync.aligned.m8n8.x4.shared.b16 {%0,%1,%2,%3}, [%4];"
                 : "=r"(r[0]), "=r"(r[1]), "=r"(r[2]), "=r"(r[3]) : "r"(addr));
}
__device__ __forceinline__ void ldsm_x2(uint32_t addr, uint32_t* r) {
    asm volatile("ldmatrix.sync.aligned.m8n8.x2.shared.b16 {%0,%1}, [%2];"
                 : "=r"(r[0]), "=r"(r[1]) : "r"(addr));
}
__device__ __forceinline__ void mma_bf16(float* c, const uint32_t* a, const uint32_t* b) {
    asm volatile(
        "mma.sync.aligned.m16n8k16.row.col.f32.bf16.bf16.f32 "
        "{%0,%1,%2,%3}, {%4,%5,%6,%7}, {%8,%9}, {%0,%1,%2,%3};"
        : "+f"(c[0]), "+f"(c[1]), "+f"(c[2]), "+f"(c[3])
        : "r"(a[0]), "r"(a[1]), "r"(a[2]), "r"(a[3]), "r"(b[0]), "r"(b[1]));
}
__device__ __forceinline__ void cp16(uint32_t dst, const void* src) {
    asm volatile("cp.async.cg.shared.global [%0], [%1], 16;" :: "r"(dst), "l"(src));
}

// fp32 -> bf16 conversion pre-pass
__global__ void cvt_kernel(const float* __restrict__ src, __nv_bfloat16* __restrict__ dst, int n4) {
    int i = blockIdx.x * blockDim.x + threadIdx.x;
    if (i < n4) {
        float4 v = ((const float4*)src)[i];
        uint2 p = make_uint2(pack_bf16(v.x, v.y), pack_bf16(v.z, v.w));
        ((uint2*)dst)[i] = p;
    }
}

// A: bf16 [Bsz*R, D]; Bm: bf16 [Bsz, W, D].
template <int NT, int WPAD>
__global__ void __launch_bounds__(256, 2)
xattn_cp_kernel(const __nv_bfloat16* __restrict__ A, const __nv_bfloat16* __restrict__ Bm,
                const int* __restrict__ cap_lens, const int* __restrict__ obj_nums,
                int R, int W, int Bsz)
{
    constexpr int BNW = NT * 8;              // cols per warp (56 or 64)
    constexpr int BN  = 2 * BNW;             // cols per CTA (112 or 128)
    constexpr int CPW = BNW / WPAD;          // captions per warp (1 or 2)
    constexpr int CAPS_PER_TILE = 2 * CPW;
    constexpr int NB4 = NT / 2;
    constexpr bool HASX2 = (NT & 1) != 0;

    extern __shared__ __align__(16) unsigned char smraw[];   // [6][STAGE_BYTES]
    const uint32_t sbase = smem_u32(smraw);

    const int tid  = threadIdx.x;
    const int wid  = tid >> 5;
    const int lane = tid & 31;
    const int g = lane >> 2;
    const int t = lane & 3;
    const int wm = wid & 3;
    const int wn = wid >> 2;
    const int m0 = blockIdx.x * BM;
    const int cbase = blockIdx.y * CAPS_PER_TILE;

    // ---- cp.async slot mapping: slot = tid + i*256; row = slot/4; c16 = slot%4
    const __nv_bfloat16* srcA[2];
    const __nv_bfloat16* srcB[2];
    bool bval[2];
    uint32_t dstOff[2];
#pragma unroll
    for (int i = 0; i < 2; i++) {
        const int slot = tid + i * 256;
        const int row  = slot >> 2;
        const int c16  = slot & 3;
        dstOff[i] = (uint32_t)(row * (SROW * 2) + c16 * 16);
        srcA[i] = A + (size_t)(m0 + row) * D + c16 * 8;
        const int cap  = row / WPAD;             // const divisor
        const int word = row - cap * WPAD;
        bval[i] = (row < BN) && (word < W);
        const int capc = (cap < CAPS_PER_TILE) ? cap : 0;
        srcB[i] = Bm + ((size_t)(cbase + capc) * W + word) * D + c16 * 8;
    }

    // zero B-stage rows that cp.async never writes (padding / row >= BN)
    {
        const uint4 z = make_uint4(0u, 0u, 0u, 0u);
        for (int idx = tid; idx < 128 * 5; idx += 256) {
            const int row = idx / 5;
            const int c   = idx - row * 5;
            const int cap  = row / WPAD;
            const int word = row - cap * WPAD;
            const bool valid = (row < BN) && (word < W);
            if (!valid) {
#pragma unroll
                for (int s = 0; s < 3; s++)
                    *(uint4*)(smraw + (3 + s) * STAGE_BYTES + row * (SROW * 2) + c * 16) = z;
            }
        }
    }

    float acc[2][NT][4];
#pragma unroll
    for (int mt = 0; mt < 2; mt++)
#pragma unroll
        for (int nt = 0; nt < NT; nt++)
#pragma unroll
            for (int e = 0; e < 4; e++) acc[mt][nt][e] = 0.0f;

    uint32_t aoff[2];
#pragma unroll
    for (int mt = 0; mt < 2; mt++)
        aoff[mt] = (uint32_t)((wm * 32 + mt * 16 + (lane & 15)) * (SROW * 2) + ((lane >> 4) << 4));
    uint32_t boff[NB4 + (HASX2 ? 1 : 0)];
#pragma unroll
    for (int nb = 0; nb < NB4; nb++) {
        const int n_local = (lane & 7) + ((lane & 16) ? 8 : 0);
        const int kb = (lane & 8) ? 16 : 0;
        boff[nb] = (uint32_t)((wn * BNW + nb * 16 + n_local) * (SROW * 2) + kb);
    }
    if (HASX2) {
        const int n_local = lane & 7;
        const int kb = (lane & 8) ? 16 : 0;
        boff[NB4] = (uint32_t)((wn * BNW + NB4 * 16 + n_local) * (SROW * 2) + kb);
    }

    auto issue = [&](int ch, int s) {
        const int off = ch * BK;     // bf16 elements
#pragma unroll
        for (int i = 0; i < 2; i++)
            cp16(sbase + s * STAGE_BYTES + dstOff[i], srcA[i] + off);
#pragma unroll
        for (int i = 0; i < 2; i++)
            if (bval[i])
                cp16(sbase + (3 + s) * STAGE_BYTES + dstOff[i], srcB[i] + off);
        asm volatile("cp.async.commit_group;" ::: "memory");
    };

    auto compute = [&](int s) {
        const uint32_t abase = sbase + s * STAGE_BYTES;
        const uint32_t bbase = sbase + (3 + s) * STAGE_BYTES;
#pragma unroll
        for (int ks = 0; ks < 2; ks++) {
            const uint32_t ko = ks * 32;
            uint32_t afr[2][4];
#pragma unroll
            for (int mt = 0; mt < 2; mt++) ldsm_x4(abase + aoff[mt] + ko, afr[mt]);
            uint32_t bfr[NB4 + (HASX2 ? 1 : 0)][4];
#pragma unroll
            for (int nb = 0; nb < NB4; nb++) ldsm_x4(bbase + boff[nb] + ko, bfr[nb]);
            if (HASX2) ldsm_x2(bbase + boff[NB4] + ko, bfr[NB4]);
#pragma unroll
            for (int mt = 0; mt < 2; mt++)
#pragma unroll
                for (int nt = 0; nt < NT; nt++)
                    mma_bf16(acc[mt][nt], afr[mt], &bfr[nt >> 1][(nt & 1) * 2]);
        }
    };

    issue(0, 0);

    for (int ch = 0; ch < NCHUNK; ch++) {
        const int s = ch % 3;
        if (ch + 1 < NCHUNK) {
            issue(ch + 1, (ch + 1) % 3);
            asm volatile("cp.async.wait_group 1;" ::: "memory");
        } else {
            asm volatile("cp.async.wait_group 0;" ::: "memory");
        }
        __syncthreads();
        compute(s);
    }

    // ---- epilogue (identical to R9)
    int clv[CPW];
#pragma unroll
    for (int cap = 0; cap < CPW; cap++)
        clv[cap] = cap_lens[cbase + wn * CPW + cap];

    float mx[2][2][CPW];
#pragma unroll
    for (int mt = 0; mt < 2; mt++)
#pragma unroll
        for (int h = 0; h < 2; h++)
#pragma unroll
            for (int cap = 0; cap < CPW; cap++)
                mx[mt][h][cap] = -1e30f;

#pragma unroll
    for (int mt = 0; mt < 2; mt++)
#pragma unroll
        for (int nt = 0; nt < NT; nt++)
#pragma unroll
            for (int e = 0; e < 2; e++) {
                const int wc = nt * 8 + 2 * t + e;
                const int cap  = wc / WPAD;
                const int wpos = wc - cap * WPAD;
                if (wpos < clv[cap]) {
                    mx[mt][0][cap] = fmaxf(mx[mt][0][cap], acc[mt][nt][e]);
                    mx[mt][1][cap] = fmaxf(mx[mt][1][cap], acc[mt][nt][2 + e]);
                }
            }

#pragma unroll
    for (int mt = 0; mt < 2; mt++)
#pragma unroll
        for (int h = 0; h < 2; h++)
#pragma unroll
            for (int cap = 0; cap < CPW; cap++) {
                float v = mx[mt][h][cap];
                v = fmaxf(v, __shfl_xor_sync(0xffffffffu, v, 1));
                v = fmaxf(v, __shfl_xor_sync(0xffffffffu, v, 2));
                if (t == 0) {
                    const int row = m0 + wm * 32 + mt * 16 + h * 8 + g;
                    const int b = row / R;
                    const float denom = (float)obj_nums[b] + 1e-6f;
                    const int c = cbase + wn * CPW + cap;
                    atomicAdd(&g_scores[b * Bsz + c], __fdividef(v, denom));
                }
            }
}

__global__ void loss_kernel(int Bsz) {
    __shared__ float red[256];
    const int tid = threadIdx.x;
    const int n = Bsz * Bsz;
    float sum = 0.0f;
    for (int idx = blockIdx.x * blockDim.x + tid; idx < n; idx += gridDim.x * blockDim.x) {
        const int i = idx / Bsz;
        const int j = idx - i * Bsz;
        if (i != j) {
            const float sc = g_scores[idx];
            const float di = g_scores[i * Bsz + i];
            const float dj = g_scores[j * Bsz + j];
            sum += fmaxf(0.0f, 0.2f + sc - di);
            sum += fmaxf(0.0f, 0.2f + sc - dj);
        }
    }
    red[tid] = sum;
    __syncthreads();
    for (int s = 128; s > 0; s >>= 1) {
        if (tid < s) red[tid] += red[tid + s];
        __syncthreads();
    }
    if (tid == 0) atomicAdd(&g_loss, red[0]);
}

__global__ void write_out_kernel(float* out, int out_size, int n) {
    const int i = blockIdx.x * blockDim.x + threadIdx.x;
    if (i >= out_size) return;
    if (out_size == n) { out[i] = g_scores[i]; return; }
    if (out_size == 1) { out[0] = g_loss; return; }
    if (i == 0) { out[0] = g_loss; return; }
    const int j = i - 1;
    out[i] = (j < n) ? g_scores[j] : 0.0f;
}

extern "C" void kernel_launch(void* const* d_in, const int* in_sizes, int n_in,
                              void* d_out, int out_size) {
    const float* im   = (const float*)d_in[0];
    const int*   im_l = (const int*)  d_in[1];
    const float* s    = (const float*)d_in[2];
    const int*   s_l  = (const int*)  d_in[3];
    const float* pred = (const float*)d_in[4];
    const int*   pr_l = (const int*)  d_in[5];
    const float* sp   = (const float*)d_in[6];
    const int*   sp_l = (const int*)  d_in[7];

    const int Bsz = in_sizes[1];                 // 128
    const int R   = in_sizes[0] / (Bsz * D);     // 36
    const int W   = in_sizes[2] / (Bsz * D);     // 50
    const int Rp  = in_sizes[4] / (Bsz * D);     // 25
    const int Wp  = in_sizes[6] / (Bsz * D);     // 30

    __nv_bfloat16* Abf;  cudaGetSymbolAddress((void**)&Abf, g_Abf);
    __nv_bfloat16* Bbf;  cudaGetSymbolAddress((void**)&Bbf, g_Bbf);

    static bool attr_set = false;
    if (!attr_set) {
        cudaFuncSetAttribute(xattn_cp_kernel<7, 56>, cudaFuncAttributeMaxDynamicSharedMemorySize, SMEM_DYN);
        cudaFuncSetAttribute(xattn_cp_kernel<8, 32>, cudaFuncAttributeMaxDynamicSharedMemorySize, SMEM_DYN);
        attr_set = true;
    }

    zero_kernel<<<(Bsz * Bsz + 255) / 256, 256>>>(Bsz * Bsz);

    // ---- part 1: convert then GEMM (W=50 -> pad 56; 1 caption/warp)
    {
        const int nA4 = M1 * D / 4, nB4 = BSZ_C * W1 * D / 4;
        cvt_kernel<<<(nA4 + 255) / 256, 256>>>(im, Abf, nA4);
        cvt_kernel<<<(nB4 + 255) / 256, 256>>>(s,  Bbf, nB4);
        dim3 g1(M1 / BM, Bsz / 2);   // (36, 64)
        xattn_cp_kernel<7, 56><<<g1, 256, SMEM_DYN>>>(Abf, Bbf, s_l, im_l, R, W, Bsz);
    }
    // ---- part 2: convert then GEMM (W=30 -> pad 32; 2 captions/warp)
    {
        const int nA4 = M2 * D / 4, nB4 = BSZ_C * W2 * D / 4;
        cvt_kernel<<<(nA4 + 255) / 256, 256>>>(pred, Abf, nA4);
        cvt_kernel<<<(nB4 + 255) / 256, 256>>>(sp,   Bbf, nB4);
        dim3 g2(M2 / BM, Bsz / 4);   // (25, 32)
        xattn_cp_kernel<8, 32><<<g2, 256, SMEM_DYN>>>(Abf, Bbf, sp_l, pr_l, Rp, Wp, Bsz);
    }

    loss_kernel<<<32, 256>>>(Bsz);
    write_out_kernel<<<(out_size + 255) / 256, 256>>>((float*)d_out, out_size, Bsz * Bsz);
}